// round 15
// baseline (speedup 1.0000x reference)
#include <cuda_runtime.h>
#include <cuda_fp16.h>
#include <math.h>
#include <stdint.h>

// ---------------------------------------------------------------------------
// Problem constants: N=50000, E=600000, IN=128, HID=64, HEADS=4, OUT=10, G=64
// ---------------------------------------------------------------------------
#define MAXN 50048
#define MAXE 600064

// Scratch (device globals — zero-initialized at load; kernels re-zero what
// they consume so every graph replay starts from a clean state).
// NOTE: g_deg pad [N, MAXN) is never written -> stays zero across replays
// (the int4 scan relies on this).
__device__ __align__(16) __half g_hH[(size_t)MAXN * 256];  // GEMM output h (fp16)
__device__ __align__(16) __half g_hG[(size_t)MAXN * 256];  // gather out L1/L2 (fp16)
__device__ __align__(16) float  g_hB3[(size_t)MAXN * 64];  // gather out L3 (fp32)
__device__ __align__(16) __half g_xh[(size_t)MAXN * 128];  // fp16 x
__device__ __align__(16) __half g_Wh[114688];              // fp16 W1^T|W2^T|W3^T [N][K]
__device__ __align__(16) float g_ex[(size_t)MAXE * 4];     // CSR-ordered exp(logit)
__device__ __align__(16) float g_als[(size_t)MAXN * 4];    // alpha_src coeffs
__device__ __align__(16) float g_ald[(size_t)MAXN * 4];    // alpha_dst coeffs
__device__ __align__(16) int g_deg[MAXN];  // zeroed by pool_acc of prev replay
__device__ int g_rowptr[MAXN + 1];
__device__ int g_cursor[MAXN];
__device__ int g_col[MAXE];        // src per CSR slot
__device__ int g_dst[MAXE];        // dst per CSR slot
__device__ __align__(16) float g_pool[64 * 64];   // zeroed by final_linear tail
__device__ __align__(16) float g_cnt[64];

// ---------------------------------------------------------------------------
// prep: fp16-convert x, fp16-transpose-convert weights, AND degree histogram,
// all in one launch. g_deg is already zero (initial load / previous replay).
// ---------------------------------------------------------------------------
__global__ void prep_kernel(const float* __restrict__ x,
                            const float* __restrict__ W1,
                            const float* __restrict__ W2,
                            const float* __restrict__ W3,
                            const int* __restrict__ ei, int N, int E)
{
    int i = blockIdx.x * blockDim.x + threadIdx.x;
    int n4 = N * 32;
    if (i < n4) {
        float4 v = ((const float4*)x)[i];
        __half2* o = (__half2*)g_xh + i * 2;
        o[0] = __floats2half2_rn(v.x, v.y);
        o[1] = __floats2half2_rn(v.z, v.w);
    }
    if (i < 114688) {
        const float* src;
        int jj, K, NN;
        if (i < 32768)      { src = W1; jj = i;          K = 128; NN = 256; }
        else if (i < 98304) { src = W2; jj = i - 32768;  K = 256; NN = 256; }
        else                { src = W3; jj = i - 98304;  K = 256; NN = 64;  }
        int n = jj / K, k = jj % K;
        g_Wh[i] = __float2half_rn(src[k * NN + n]);
    }
    if (i < E) atomicAdd(&g_deg[ei[E + i]], 1);
}

// ---------------------------------------------------------------------------
// fp16 tensor-core GEMM (m16n8k16, ldmatrix), cp.async 2-stage pipeline,
// fused attn-coef epilogue. A fp16 [M][K]; Bt fp16 [N][K] (transposed weight).
// BM=128, BN=64(=one head), BK=32. 8 warps; warp tile 32x32.
// Smem chunk swizzle: 16B chunk q at row r lives at q ^ ((r>>1)&3).
// ---------------------------------------------------------------------------
__global__ __launch_bounds__(256, 3) void h16_gemm_kernel(
    const __half* __restrict__ A, const __half* __restrict__ Bt,
    __half* __restrict__ Ch, int M, int N, int K,
    const float* __restrict__ asrc, const float* __restrict__ adst,
    float* __restrict__ als, float* __restrict__ ald, int H)
{
    __shared__ __align__(16) __half As[2][128 * 32];   // 8KB per buffer
    __shared__ __align__(16) __half Bs[2][64 * 32];    // 4KB per buffer

    int tid = threadIdx.x;
    int warp = tid >> 5, lane = tid & 31;
    int gid = lane >> 2, tig = lane & 3;
    int wm = warp & 3, wn = warp >> 2;           // wm 0..3 (M), wn 0..1 (N)
    int rowBase = blockIdx.y * 128;
    int colBase = blockIdx.x * 64;

    uint32_t asBase, bsBase;
    asm("{ .reg .u64 t; cvta.to.shared.u64 t, %1; cvt.u32.u64 %0, t; }"
        : "=r"(asBase) : "l"(&As[0][0]));
    asm("{ .reg .u64 t; cvta.to.shared.u64 t, %1; cvt.u32.u64 %0, t; }"
        : "=r"(bsBase) : "l"(&Bs[0][0]));

    float acc[2][4][4];
#pragma unroll
    for (int i = 0; i < 2; i++)
#pragma unroll
        for (int j = 0; j < 4; j++)
#pragma unroll
            for (int r = 0; r < 4; r++) acc[i][j][r] = 0.f;

    auto issue = [&](int k0, int buf) {
#pragma unroll
        for (int i = 0; i < 2; i++) {
            int f = tid + i * 256;
            int m = f >> 2, q = f & 3;
            int qs = q ^ ((m >> 1) & 3);
            int gr = rowBase + m;
            const __half* src = A + (size_t)(gr < M ? gr : M - 1) * K + k0 + q * 8;
            int sz = (gr < M) ? 16 : 0;
            uint32_t dst = asBase + buf * 8192 + m * 64 + qs * 16;
            asm volatile("cp.async.cg.shared.global [%0], [%1], 16, %2;"
                         :: "r"(dst), "l"(src), "r"(sz));
        }
        {
            int n = tid >> 2, q = tid & 3;
            int qs = q ^ ((n >> 1) & 3);
            const __half* src = Bt + (size_t)(colBase + n) * K + k0 + q * 8;
            uint32_t dst = bsBase + buf * 4096 + n * 64 + qs * 16;
            asm volatile("cp.async.cg.shared.global [%0], [%1], 16;"
                         :: "r"(dst), "l"(src));
        }
        asm volatile("cp.async.commit_group;");
    };

    auto compute = [&](int buf) {
        uint32_t aB = asBase + buf * 8192;
        uint32_t bB = bsBase + buf * 4096;
        int lrow = lane & 15;
        int chHalf = lane >> 4;                     // which k8-chunk within kstep
#pragma unroll
        for (int ks = 0; ks < 2; ks++) {
            int ch = ks * 2 + chHalf;
            uint32_t a[2][4], b[2][4];
#pragma unroll
            for (int mf = 0; mf < 2; mf++) {
                int row = (wm * 2 + mf) * 16 + lrow;
                uint32_t addr = aB + row * 64 + ((ch ^ ((row >> 1) & 3)) * 16);
                asm volatile(
                    "ldmatrix.sync.aligned.m8n8.x4.shared.b16 {%0,%1,%2,%3}, [%4];"
                    : "=r"(a[mf][0]), "=r"(a[mf][1]), "=r"(a[mf][2]), "=r"(a[mf][3])
                    : "r"(addr));
            }
#pragma unroll
            for (int pr = 0; pr < 2; pr++) {
                int n = wn * 32 + pr * 16 + lrow;
                uint32_t addr = bB + n * 64 + ((ch ^ ((n >> 1) & 3)) * 16);
                asm volatile(
                    "ldmatrix.sync.aligned.m8n8.x4.shared.b16 {%0,%1,%2,%3}, [%4];"
                    : "=r"(b[pr][0]), "=r"(b[pr][1]), "=r"(b[pr][2]), "=r"(b[pr][3])
                    : "r"(addr));
            }
#pragma unroll
            for (int mf = 0; mf < 2; mf++)
#pragma unroll
                for (int nf = 0; nf < 4; nf++) {
                    int pr = nf >> 1, sub = nf & 1;
                    asm volatile(
                        "mma.sync.aligned.m16n8k16.row.col.f32.f16.f16.f32 "
                        "{%0,%1,%2,%3},{%4,%5,%6,%7},{%8,%9},{%0,%1,%2,%3};"
                        : "+f"(acc[mf][nf][0]), "+f"(acc[mf][nf][1]),
                          "+f"(acc[mf][nf][2]), "+f"(acc[mf][nf][3])
                        : "r"(a[mf][0]), "r"(a[mf][1]), "r"(a[mf][2]), "r"(a[mf][3]),
                          "r"(b[pr][sub]), "r"(b[pr][sub + 2]));
                }
        }
    };

    int nt = K >> 5;             // K/32 tiles
    issue(0, 0);
    int buf = 0;
    for (int t = 0; t < nt; t++) {
        if (t + 1 < nt) issue((t + 1) * 32, buf ^ 1);
        else            asm volatile("cp.async.commit_group;");
        asm volatile("cp.async.wait_group 1;");
        __syncthreads();
        compute(buf);
        __syncthreads();
        buf ^= 1;
    }

    // C store (fp16): c0/c1 at (row0, col..col+1); c2/c3 at row0+8.
#pragma unroll
    for (int mf = 0; mf < 2; mf++) {
        int row0 = rowBase + (wm * 2 + mf) * 16 + gid;
#pragma unroll
        for (int nf = 0; nf < 4; nf++) {
            int col = colBase + (wn * 4 + nf) * 8 + tig * 2;
            if (row0 < M)
                *(__half2*)(Ch + (size_t)row0 * N + col) =
                    __floats2half2_rn(acc[mf][nf][0], acc[mf][nf][1]);
            if (row0 + 8 < M)
                *(__half2*)(Ch + (size_t)(row0 + 8) * N + col) =
                    __floats2half2_rn(acc[mf][nf][2], acc[mf][nf][3]);
        }
    }

    // ---- fused attn-coef epilogue: als/ald row dots for this head ----
    {
        int hd = blockIdx.x;                       // BN == C == 64
        const float* ah = asrc + hd * 64;
        const float* dh = adst + hd * 64;
        float* sred = (float*)&As[0][0];           // post-loop: buffers free
        float ps[2][2][2];                         // [mf][half][src/dst]
#pragma unroll
        for (int mf = 0; mf < 2; mf++) {
            float s0 = 0.f, s1 = 0.f, t0 = 0.f, t1 = 0.f;
#pragma unroll
            for (int nf = 0; nf < 4; nf++) {
                int l = (wn * 4 + nf) * 8 + tig * 2;
                float a0 = ah[l], a1 = ah[l + 1];
                float d0 = dh[l], d1 = dh[l + 1];
                s0 += acc[mf][nf][0] * a0 + acc[mf][nf][1] * a1;
                s1 += acc[mf][nf][2] * a0 + acc[mf][nf][3] * a1;
                t0 += acc[mf][nf][0] * d0 + acc[mf][nf][1] * d1;
                t1 += acc[mf][nf][2] * d0 + acc[mf][nf][3] * d1;
            }
            ps[mf][0][0] = s0; ps[mf][1][0] = s1;
            ps[mf][0][1] = t0; ps[mf][1][1] = t1;
        }
#pragma unroll
        for (int mf = 0; mf < 2; mf++)
#pragma unroll
            for (int hf = 0; hf < 2; hf++)
#pragma unroll
                for (int q = 0; q < 2; q++) {
                    ps[mf][hf][q] += __shfl_xor_sync(0xFFFFFFFF, ps[mf][hf][q], 1);
                    ps[mf][hf][q] += __shfl_xor_sync(0xFFFFFFFF, ps[mf][hf][q], 2);
                }
        if (tig == 0 && wn == 0) {
#pragma unroll
            for (int mf = 0; mf < 2; mf++)
#pragma unroll
                for (int hf = 0; hf < 2; hf++) {
                    int rl = (wm * 2 + mf) * 16 + hf * 8 + gid;
                    sred[rl * 2 + 0] = ps[mf][hf][0];
                    sred[rl * 2 + 1] = ps[mf][hf][1];
                }
        }
        __syncthreads();
        if (tig == 0 && wn == 1) {
#pragma unroll
            for (int mf = 0; mf < 2; mf++)
#pragma unroll
                for (int hf = 0; hf < 2; hf++) {
                    int rl = (wm * 2 + mf) * 16 + hf * 8 + gid;
                    int row = rowBase + rl;
                    if (row < M) {
                        als[row * H + hd] = ps[mf][hf][0] + sred[rl * 2 + 0];
                        ald[row * H + hd] = ps[mf][hf][1] + sred[rl * 2 + 1];
                    }
                }
        }
    }
}

// ---------------------------------------------------------------------------
// Single-block exclusive scan, 4 elements/thread (4096/iter). Pad of g_deg
// beyond N is permanently zero (never written), so int4 reads are safe.
// ---------------------------------------------------------------------------
__global__ __launch_bounds__(1024) void csr_scan_kernel(int N)
{
    __shared__ int wsum[32];
    __shared__ int carry;
    int tid = threadIdx.x;
    int lane = tid & 31, w = tid >> 5;
    if (tid == 0) { carry = 0; g_rowptr[0] = 0; }
    __syncthreads();
    for (int base = 0; base < N; base += 4096) {
        int i4 = base / 4 + tid;
        int4 v = make_int4(0, 0, 0, 0);
        if (i4 < MAXN / 4) v = ((const int4*)g_deg)[i4];
        int s4 = v.x + v.y + v.z + v.w;
        int x = s4;
#pragma unroll
        for (int off = 1; off < 32; off <<= 1) {
            int t = __shfl_up_sync(0xFFFFFFFF, x, off);
            if (lane >= off) x += t;
        }
        if (lane == 31) wsum[w] = x;
        __syncthreads();
        if (w == 0) {
            int s = wsum[lane];
#pragma unroll
            for (int off = 1; off < 32; off <<= 1) {
                int t = __shfl_up_sync(0xFFFFFFFF, s, off);
                if (lane >= off) s += t;
            }
            wsum[lane] = s;
        }
        __syncthreads();
        int incl = x + (w > 0 ? wsum[w - 1] : 0);
        int c = carry;
        int e = c + incl - s4;
        int idx = i4 * 4;
        if (idx < N)     { g_cursor[idx]     = e; g_rowptr[idx + 1] = e + v.x; }
        e += v.x;
        if (idx + 1 < N) { g_cursor[idx + 1] = e; g_rowptr[idx + 2] = e + v.y; }
        e += v.y;
        if (idx + 2 < N) { g_cursor[idx + 2] = e; g_rowptr[idx + 3] = e + v.z; }
        e += v.z;
        if (idx + 3 < N) { g_cursor[idx + 3] = e; g_rowptr[idx + 4] = e + v.w; }
        __syncthreads();
        if (tid == 1023) carry = c + incl;
        __syncthreads();
    }
}

// csr_fill fused with layer-1 edge exp, 2 edges per thread (MLP=2 on the
// atomic + scattered-gather latency chains). als/ald from GEMM1 are ready.
__global__ void csr_fill_ex4_kernel(const int* __restrict__ ei, int E,
                                    const float* __restrict__ als,
                                    const float* __restrict__ ald)
{
    int e0 = (blockIdx.x * blockDim.x + threadIdx.x) * 2;
    if (e0 >= E) return;
    bool two = (e0 + 1 < E);
    int2 ss = *(const int2*)&ei[e0];
    int2 dd = *(const int2*)&ei[E + e0];
    int p0 = atomicAdd(&g_cursor[dd.x], 1);
    int p1 = two ? atomicAdd(&g_cursor[dd.y], 1) : 0;
    float4 a0 = *(const float4*)&als[ss.x * 4];
    float4 b0 = *(const float4*)&ald[dd.x * 4];
    float4 a1 = two ? *(const float4*)&als[ss.y * 4] : make_float4(0, 0, 0, 0);
    float4 b1 = two ? *(const float4*)&ald[dd.y * 4] : make_float4(0, 0, 0, 0);

    g_col[p0] = ss.x;
    g_dst[p0] = dd.x;
    float4 v;
    v.x = a0.x + b0.x; v.x = (v.x > 0.f) ? v.x : 0.2f * v.x; v.x = __expf(v.x);
    v.y = a0.y + b0.y; v.y = (v.y > 0.f) ? v.y : 0.2f * v.y; v.y = __expf(v.y);
    v.z = a0.z + b0.z; v.z = (v.z > 0.f) ? v.z : 0.2f * v.z; v.z = __expf(v.z);
    v.w = a0.w + b0.w; v.w = (v.w > 0.f) ? v.w : 0.2f * v.w; v.w = __expf(v.w);
    *(float4*)&g_ex[(size_t)p0 * 4] = v;

    if (two) {
        g_col[p1] = ss.y;
        g_dst[p1] = dd.y;
        v.x = a1.x + b1.x; v.x = (v.x > 0.f) ? v.x : 0.2f * v.x; v.x = __expf(v.x);
        v.y = a1.y + b1.y; v.y = (v.y > 0.f) ? v.y : 0.2f * v.y; v.y = __expf(v.y);
        v.z = a1.z + b1.z; v.z = (v.z > 0.f) ? v.z : 0.2f * v.z; v.z = __expf(v.z);
        v.w = a1.w + b1.w; v.w = (v.w > 0.f) ? v.w : 0.2f * v.w; v.w = __expf(v.w);
        *(float4*)&g_ex[(size_t)p1 * 4] = v;
    }
}

// ---------------------------------------------------------------------------
// Edge exp (layers 2/3): ex[p,h] = exp(leaky_relu(als[src]+ald[dst])).
// ---------------------------------------------------------------------------
__global__ void edge_ex4_kernel(int E, const float* __restrict__ als,
                                const float* __restrict__ ald)
{
    int p = blockIdx.x * blockDim.x + threadIdx.x;
    if (p >= E) return;
    int s = g_col[p], d = g_dst[p];
    float4 a = *(const float4*)&als[s * 4];
    float4 b = *(const float4*)&ald[d * 4];
    float4 v;
    v.x = a.x + b.x; v.x = (v.x > 0.f) ? v.x : 0.2f * v.x; v.x = __expf(v.x);
    v.y = a.y + b.y; v.y = (v.y > 0.f) ? v.y : 0.2f * v.y; v.y = __expf(v.y);
    v.z = a.z + b.z; v.z = (v.z > 0.f) ? v.z : 0.2f * v.z; v.z = __expf(v.z);
    v.w = a.w + b.w; v.w = (v.w > 0.f) ? v.w : 0.2f * v.w; v.w = __expf(v.w);
    *(float4*)&g_ex[(size_t)p * 4] = v;
}

__global__ void edge_ex1_kernel(int E, const float* __restrict__ als,
                                const float* __restrict__ ald)
{
    int p = blockIdx.x * blockDim.x + threadIdx.x;
    if (p >= E) return;
    float v = als[g_col[p]] + ald[g_dst[p]];
    v = (v > 0.f) ? v : 0.2f * v;
    g_ex[p] = __expf(v);
}

// ---------------------------------------------------------------------------
// Gather (fp16 messages) + softmax-normalize + bias + ELU. TPE = HC/8 threads
// per dst; one uint4 (8 halves) per edge per thread. Output fp16 (HALF_OUT,
// feeds next GEMM) or fp32 (final layer, feeds pooling).
// ---------------------------------------------------------------------------
__device__ __forceinline__ void unpack8(uint4 r, float* v)
{
    float2 p;
    p = __half22float2(*(__half2*)&r.x); v[0] = p.x; v[1] = p.y;
    p = __half22float2(*((__half2*)&r.x + 1)); v[2] = p.x; v[3] = p.y;
    p = __half22float2(*(__half2*)&r.z); v[4] = p.x; v[5] = p.y;
    p = __half22float2(*((__half2*)&r.z + 1)); v[6] = p.x; v[7] = p.y;
}

template <int H, int C, bool HALF_OUT>
__global__ __launch_bounds__(256) void gather_kernel(
    int N, const __half* __restrict__ h,
    const float* __restrict__ als, const float* __restrict__ ald,
    const float* __restrict__ bias, void* __restrict__ outv)
{
    constexpr int HC = H * C;
    constexpr int TPE = HC / 8;
    constexpr int DPB = 256 / TPE;
    int d = blockIdx.x * DPB + threadIdx.x / TPE;
    if (d >= N) return;
    int t = threadIdx.x % TPE;
    int hd = t / (C / 8);

    // self-loop
    float l = als[d * H + hd] + ald[d * H + hd];
    l = (l > 0.f) ? l : 0.2f * l;
    float exs = __expf(l);
    float den = exs;
    float acc[8], v[8];
    uint4 raw = *(const uint4*)(h + (size_t)d * HC + t * 8);
    unpack8(raw, v);
#pragma unroll
    for (int i = 0; i < 8; i++) acc[i] = exs * v[i];

    int p = g_rowptr[d], pend = g_rowptr[d + 1];
    for (; p < pend; p++) {
        int s = g_col[p];
        float ex = g_ex[(size_t)p * H + hd];
        raw = *(const uint4*)(h + (size_t)s * HC + t * 8);
        unpack8(raw, v);
#pragma unroll
        for (int i = 0; i < 8; i++) acc[i] += ex * v[i];
        den += ex;
    }
    float inv = 1.f / (den + 1e-16f);
    float4 bv0 = *(const float4*)(bias + t * 8);
    float4 bv1 = *(const float4*)(bias + t * 8 + 4);
    float bb[8] = {bv0.x, bv0.y, bv0.z, bv0.w, bv1.x, bv1.y, bv1.z, bv1.w};
    float o[8];
#pragma unroll
    for (int i = 0; i < 8; i++) {
        float x = acc[i] * inv + bb[i];
        o[i] = (x > 0.f) ? x : expm1f(x);
    }
    if (HALF_OUT) {
        __half2 ho[4];
#pragma unroll
        for (int i = 0; i < 4; i++) ho[i] = __floats2half2_rn(o[2 * i], o[2 * i + 1]);
        *(uint4*)((__half*)outv + (size_t)d * HC + t * 8) = *(uint4*)ho;
    } else {
        float* op = (float*)outv + (size_t)d * HC + t * 8;
        *(float4*)op = make_float4(o[0], o[1], o[2], o[3]);
        *(float4*)(op + 4) = make_float4(o[4], o[5], o[6], o[7]);
    }
}

// ---------------------------------------------------------------------------
// Pooling (batch is sorted): run-length local accumulate, rare atomic flush.
// Also re-zeroes g_deg (dead by now) for the NEXT graph replay.
// ---------------------------------------------------------------------------
__global__ __launch_bounds__(256) void pool_acc_kernel(
    const float* __restrict__ h, const int* __restrict__ batch, int N)
{
    int gidx = blockIdx.x * 256 + threadIdx.x;
    if (gidx < N) g_deg[gidx] = 0;     // cleanup for next replay

    int c = threadIdx.x & 63;
    int lane = threadIdx.x >> 6;
    int n0 = blockIdx.x * 64 + lane * 16;
    float acc = 0.f;
    int curg = -1, cnt = 0;
    for (int k = 0; k < 16; k++) {
        int n = n0 + k;
        if (n >= N) break;
        int g = batch[n];
        if (g != curg) {
            if (curg >= 0) {
                atomicAdd(&g_pool[curg * 64 + c], acc);
                if (c == 0) atomicAdd(&g_cnt[curg], (float)cnt);
            }
            curg = g; acc = 0.f; cnt = 0;
        }
        acc += h[(size_t)n * 64 + c];
        cnt++;
    }
    if (curg >= 0) {
        atomicAdd(&g_pool[curg * 64 + c], acc);
        if (c == 0) atomicAdd(&g_cnt[curg], (float)cnt);
    }
}

// Single block (640 threads): compute output, then re-zero g_pool/g_cnt for
// the next replay (block-wide sync makes the read-then-zero race-free).
__global__ __launch_bounds__(640) void final_linear_kernel(
    const float* __restrict__ linW, const float* __restrict__ linb,
    float* __restrict__ out)
{
    int idx = threadIdx.x;
    if (idx < 640) {
        int g = idx / 10, o = idx % 10;
        float inv = 1.f / fmaxf(g_cnt[g], 1.f);
        float s = 0.f;
#pragma unroll 8
        for (int k = 0; k < 64; k++)
            s += g_pool[g * 64 + k] * inv * linW[k * 10 + o];
        out[idx] = s + linb[o];
    }
    __syncthreads();
    for (int i = threadIdx.x; i < 64 * 64; i += 640) g_pool[i] = 0.f;
    if (threadIdx.x < 64) g_cnt[threadIdx.x] = 0.f;
}

// ---------------------------------------------------------------------------
// Host orchestration (single stream; fill_ex is user launch #4 — profiled).
// ---------------------------------------------------------------------------
extern "C" void kernel_launch(void* const* d_in, const int* in_sizes, int n_in,
                              void* d_out, int out_size)
{
    const float* x     = (const float*)d_in[0];
    const int*   ei    = (const int*)d_in[1];
    const int*   batch = (const int*)d_in[2];
    const float* W1 = (const float*)d_in[3];   const float* b1 = (const float*)d_in[4];
    const float* as1 = (const float*)d_in[5];  const float* ad1 = (const float*)d_in[6];
    const float* W2 = (const float*)d_in[7];   const float* b2 = (const float*)d_in[8];
    const float* as2 = (const float*)d_in[9];  const float* ad2 = (const float*)d_in[10];
    const float* W3 = (const float*)d_in[11];  const float* b3 = (const float*)d_in[12];
    const float* as3 = (const float*)d_in[13]; const float* ad3 = (const float*)d_in[14];
    const float* linW = (const float*)d_in[15]; const float* linb = (const float*)d_in[16];
    float* out = (float*)d_out;

    int N = in_sizes[0] / 128;
    int E = in_sizes[1] / 2;

    float *als, *ald, *hB3;
    __half *hH, *hG, *xh, *Wh;
    cudaGetSymbolAddress((void**)&hH,  g_hH);
    cudaGetSymbolAddress((void**)&hG,  g_hG);
    cudaGetSymbolAddress((void**)&hB3, g_hB3);
    cudaGetSymbolAddress((void**)&als, g_als);
    cudaGetSymbolAddress((void**)&ald, g_ald);
    cudaGetSymbolAddress((void**)&xh,  g_xh);
    cudaGetSymbolAddress((void**)&Wh,  g_Wh);

    int gemmRows = (N + 127) / 128;

    // 1: prep (converts + degree histogram; g_deg pre-zeroed by prior replay)
    prep_kernel<<<(N * 32 + 255) / 256, 256>>>(x, W1, W2, W3, ei, N, E);

    // 2: layer-1 GEMM (+ fused attn coefs)
    h16_gemm_kernel<<<dim3(4, gemmRows), 256>>>(xh, Wh, hH, N, 256, 128,
                                                as1, ad1, als, ald, 4);
    // 3: CSR scan   4: fill + layer-1 edge exp (2 edges/thread)  <-- profiled
    csr_scan_kernel<<<1, 1024>>>(N);
    csr_fill_ex4_kernel<<<(E / 2 + 255) / 256, 256>>>(ei, E, als, ald);

    // Layer 1 gather (fp16 out: feeds GEMM2)
    gather_kernel<4, 64, true><<<(N + 7) / 8, 256>>>(N, hH, als, ald, b1, hG);

    // Layer 2
    h16_gemm_kernel<<<dim3(4, gemmRows), 256>>>(hG, Wh + 32768, hH, N, 256, 256,
                                                as2, ad2, als, ald, 4);
    edge_ex4_kernel<<<(E + 255) / 256, 256>>>(E, als, ald);
    gather_kernel<4, 64, true><<<(N + 7) / 8, 256>>>(N, hH, als, ald, b2, hG);

    // Layer 3 (fp32 out: feeds pooling)
    h16_gemm_kernel<<<dim3(1, gemmRows), 256>>>(hG, Wh + 98304, hH, N, 64, 256,
                                                as3, ad3, als, ald, 1);
    edge_ex1_kernel<<<(E + 255) / 256, 256>>>(E, als, ald);
    gather_kernel<1, 64, false><<<(N + 31) / 32, 256>>>(N, hH, als, ald, b3, hB3);

    // Pool (+ g_deg cleanup) + final linear (+ g_pool/g_cnt cleanup)
    pool_acc_kernel<<<(N + 63) / 64, 256>>>(hB3, batch, N);
    final_linear_kernel<<<1, 640>>>(linW, linb, out);
}

// round 16
// speedup vs baseline: 1.0039x; 1.0039x over previous
#include <cuda_runtime.h>
#include <cuda_fp16.h>
#include <math.h>
#include <stdint.h>

// ---------------------------------------------------------------------------
// Problem constants: N=50000, E=600000, IN=128, HID=64, HEADS=4, OUT=10, G=64
// ---------------------------------------------------------------------------
#define MAXN 50048
#define MAXE 600064

// Scratch (device globals — zero-initialized at load; kernels re-zero what
// they consume so every graph replay starts from a clean state).
// NOTE: g_deg pad [N, MAXN) is never written -> stays zero across replays
// (the int4 scan relies on this).
__device__ __align__(16) __half g_hH[(size_t)MAXN * 256];  // GEMM output h (fp16)
__device__ __align__(16) __half g_hG[(size_t)MAXN * 256];  // gather out L1/L2 (fp16)
__device__ __align__(16) float  g_hB3[(size_t)MAXN * 64];  // gather out L3 (fp32)
__device__ __align__(16) __half g_xh[(size_t)MAXN * 128];  // fp16 x
__device__ __align__(16) __half g_Wh[114688];              // fp16 W1^T|W2^T|W3^T [N][K]
__device__ __align__(16) float g_ex[(size_t)MAXE * 4];     // CSR-ordered exp(logit)
__device__ __align__(16) float g_als[(size_t)MAXN * 4];    // alpha_src coeffs
__device__ __align__(16) float g_ald[(size_t)MAXN * 4];    // alpha_dst coeffs
__device__ __align__(16) int g_deg[MAXN];  // zeroed by pool_acc of prev replay
__device__ int g_rowptr[MAXN + 1];
__device__ int g_cursor[MAXN];
__device__ int g_col[MAXE];        // src per CSR slot
__device__ int g_dst[MAXE];        // dst per CSR slot
__device__ __align__(16) float g_pool[64 * 64];   // zeroed by final_linear tail
__device__ __align__(16) float g_cnt[64];

// ---------------------------------------------------------------------------
// prep: fp16-convert x, fp16-transpose-convert weights, AND degree histogram,
// all in one launch. g_deg is already zero (initial load / previous replay).
// ---------------------------------------------------------------------------
__global__ void prep_kernel(const float* __restrict__ x,
                            const float* __restrict__ W1,
                            const float* __restrict__ W2,
                            const float* __restrict__ W3,
                            const int* __restrict__ ei, int N, int E)
{
    int i = blockIdx.x * blockDim.x + threadIdx.x;
    int n4 = N * 32;
    if (i < n4) {
        float4 v = ((const float4*)x)[i];
        __half2* o = (__half2*)g_xh + i * 2;
        o[0] = __floats2half2_rn(v.x, v.y);
        o[1] = __floats2half2_rn(v.z, v.w);
    }
    if (i < 114688) {
        const float* src;
        int jj, K, NN;
        if (i < 32768)      { src = W1; jj = i;          K = 128; NN = 256; }
        else if (i < 98304) { src = W2; jj = i - 32768;  K = 256; NN = 256; }
        else                { src = W3; jj = i - 98304;  K = 256; NN = 64;  }
        int n = jj / K, k = jj % K;
        g_Wh[i] = __float2half_rn(src[k * NN + n]);
    }
    if (i < E) atomicAdd(&g_deg[ei[E + i]], 1);
}

// ---------------------------------------------------------------------------
// fp16 tensor-core GEMM (m16n8k16, ldmatrix), cp.async 2-stage pipeline,
// fused attn-coef epilogue. A fp16 [M][K]; Bt fp16 [N][K] (transposed weight).
// BM=128, BN=64(=one head), BK=32. 8 warps; warp tile 32x32.
// Smem chunk swizzle: 16B chunk q at row r lives at q ^ ((r>>1)&3).
// ---------------------------------------------------------------------------
__global__ __launch_bounds__(256, 3) void h16_gemm_kernel(
    const __half* __restrict__ A, const __half* __restrict__ Bt,
    __half* __restrict__ Ch, int M, int N, int K,
    const float* __restrict__ asrc, const float* __restrict__ adst,
    float* __restrict__ als, float* __restrict__ ald, int H)
{
    __shared__ __align__(16) __half As[2][128 * 32];   // 8KB per buffer
    __shared__ __align__(16) __half Bs[2][64 * 32];    // 4KB per buffer

    int tid = threadIdx.x;
    int warp = tid >> 5, lane = tid & 31;
    int gid = lane >> 2, tig = lane & 3;
    int wm = warp & 3, wn = warp >> 2;           // wm 0..3 (M), wn 0..1 (N)
    int rowBase = blockIdx.y * 128;
    int colBase = blockIdx.x * 64;

    uint32_t asBase, bsBase;
    asm("{ .reg .u64 t; cvta.to.shared.u64 t, %1; cvt.u32.u64 %0, t; }"
        : "=r"(asBase) : "l"(&As[0][0]));
    asm("{ .reg .u64 t; cvta.to.shared.u64 t, %1; cvt.u32.u64 %0, t; }"
        : "=r"(bsBase) : "l"(&Bs[0][0]));

    float acc[2][4][4];
#pragma unroll
    for (int i = 0; i < 2; i++)
#pragma unroll
        for (int j = 0; j < 4; j++)
#pragma unroll
            for (int r = 0; r < 4; r++) acc[i][j][r] = 0.f;

    auto issue = [&](int k0, int buf) {
#pragma unroll
        for (int i = 0; i < 2; i++) {
            int f = tid + i * 256;
            int m = f >> 2, q = f & 3;
            int qs = q ^ ((m >> 1) & 3);
            int gr = rowBase + m;
            const __half* src = A + (size_t)(gr < M ? gr : M - 1) * K + k0 + q * 8;
            int sz = (gr < M) ? 16 : 0;
            uint32_t dst = asBase + buf * 8192 + m * 64 + qs * 16;
            asm volatile("cp.async.cg.shared.global [%0], [%1], 16, %2;"
                         :: "r"(dst), "l"(src), "r"(sz));
        }
        {
            int n = tid >> 2, q = tid & 3;
            int qs = q ^ ((n >> 1) & 3);
            const __half* src = Bt + (size_t)(colBase + n) * K + k0 + q * 8;
            uint32_t dst = bsBase + buf * 4096 + n * 64 + qs * 16;
            asm volatile("cp.async.cg.shared.global [%0], [%1], 16;"
                         :: "r"(dst), "l"(src));
        }
        asm volatile("cp.async.commit_group;");
    };

    auto compute = [&](int buf) {
        uint32_t aB = asBase + buf * 8192;
        uint32_t bB = bsBase + buf * 4096;
        int lrow = lane & 15;
        int chHalf = lane >> 4;                     // which k8-chunk within kstep
#pragma unroll
        for (int ks = 0; ks < 2; ks++) {
            int ch = ks * 2 + chHalf;
            uint32_t a[2][4], b[2][4];
#pragma unroll
            for (int mf = 0; mf < 2; mf++) {
                int row = (wm * 2 + mf) * 16 + lrow;
                uint32_t addr = aB + row * 64 + ((ch ^ ((row >> 1) & 3)) * 16);
                asm volatile(
                    "ldmatrix.sync.aligned.m8n8.x4.shared.b16 {%0,%1,%2,%3}, [%4];"
                    : "=r"(a[mf][0]), "=r"(a[mf][1]), "=r"(a[mf][2]), "=r"(a[mf][3])
                    : "r"(addr));
            }
#pragma unroll
            for (int pr = 0; pr < 2; pr++) {
                int n = wn * 32 + pr * 16 + lrow;
                uint32_t addr = bB + n * 64 + ((ch ^ ((n >> 1) & 3)) * 16);
                asm volatile(
                    "ldmatrix.sync.aligned.m8n8.x4.shared.b16 {%0,%1,%2,%3}, [%4];"
                    : "=r"(b[pr][0]), "=r"(b[pr][1]), "=r"(b[pr][2]), "=r"(b[pr][3])
                    : "r"(addr));
            }
#pragma unroll
            for (int mf = 0; mf < 2; mf++)
#pragma unroll
                for (int nf = 0; nf < 4; nf++) {
                    int pr = nf >> 1, sub = nf & 1;
                    asm volatile(
                        "mma.sync.aligned.m16n8k16.row.col.f32.f16.f16.f32 "
                        "{%0,%1,%2,%3},{%4,%5,%6,%7},{%8,%9},{%0,%1,%2,%3};"
                        : "+f"(acc[mf][nf][0]), "+f"(acc[mf][nf][1]),
                          "+f"(acc[mf][nf][2]), "+f"(acc[mf][nf][3])
                        : "r"(a[mf][0]), "r"(a[mf][1]), "r"(a[mf][2]), "r"(a[mf][3]),
                          "r"(b[pr][sub]), "r"(b[pr][sub + 2]));
                }
        }
    };

    int nt = K >> 5;             // K/32 tiles
    issue(0, 0);
    int buf = 0;
    for (int t = 0; t < nt; t++) {
        if (t + 1 < nt) issue((t + 1) * 32, buf ^ 1);
        else            asm volatile("cp.async.commit_group;");
        asm volatile("cp.async.wait_group 1;");
        __syncthreads();
        compute(buf);
        __syncthreads();
        buf ^= 1;
    }

    // C store (fp16): c0/c1 at (row0, col..col+1); c2/c3 at row0+8.
#pragma unroll
    for (int mf = 0; mf < 2; mf++) {
        int row0 = rowBase + (wm * 2 + mf) * 16 + gid;
#pragma unroll
        for (int nf = 0; nf < 4; nf++) {
            int col = colBase + (wn * 4 + nf) * 8 + tig * 2;
            if (row0 < M)
                *(__half2*)(Ch + (size_t)row0 * N + col) =
                    __floats2half2_rn(acc[mf][nf][0], acc[mf][nf][1]);
            if (row0 + 8 < M)
                *(__half2*)(Ch + (size_t)(row0 + 8) * N + col) =
                    __floats2half2_rn(acc[mf][nf][2], acc[mf][nf][3]);
        }
    }

    // ---- fused attn-coef epilogue: als/ald row dots for this head ----
    {
        int hd = blockIdx.x;                       // BN == C == 64
        const float* ah = asrc + hd * 64;
        const float* dh = adst + hd * 64;
        float* sred = (float*)&As[0][0];           // post-loop: buffers free
        float ps[2][2][2];                         // [mf][half][src/dst]
#pragma unroll
        for (int mf = 0; mf < 2; mf++) {
            float s0 = 0.f, s1 = 0.f, t0 = 0.f, t1 = 0.f;
#pragma unroll
            for (int nf = 0; nf < 4; nf++) {
                int l = (wn * 4 + nf) * 8 + tig * 2;
                float a0 = ah[l], a1 = ah[l + 1];
                float d0 = dh[l], d1 = dh[l + 1];
                s0 += acc[mf][nf][0] * a0 + acc[mf][nf][1] * a1;
                s1 += acc[mf][nf][2] * a0 + acc[mf][nf][3] * a1;
                t0 += acc[mf][nf][0] * d0 + acc[mf][nf][1] * d1;
                t1 += acc[mf][nf][2] * d0 + acc[mf][nf][3] * d1;
            }
            ps[mf][0][0] = s0; ps[mf][1][0] = s1;
            ps[mf][0][1] = t0; ps[mf][1][1] = t1;
        }
#pragma unroll
        for (int mf = 0; mf < 2; mf++)
#pragma unroll
            for (int hf = 0; hf < 2; hf++)
#pragma unroll
                for (int q = 0; q < 2; q++) {
                    ps[mf][hf][q] += __shfl_xor_sync(0xFFFFFFFF, ps[mf][hf][q], 1);
                    ps[mf][hf][q] += __shfl_xor_sync(0xFFFFFFFF, ps[mf][hf][q], 2);
                }
        if (tig == 0 && wn == 0) {
#pragma unroll
            for (int mf = 0; mf < 2; mf++)
#pragma unroll
                for (int hf = 0; hf < 2; hf++) {
                    int rl = (wm * 2 + mf) * 16 + hf * 8 + gid;
                    sred[rl * 2 + 0] = ps[mf][hf][0];
                    sred[rl * 2 + 1] = ps[mf][hf][1];
                }
        }
        __syncthreads();
        if (tig == 0 && wn == 1) {
#pragma unroll
            for (int mf = 0; mf < 2; mf++)
#pragma unroll
                for (int hf = 0; hf < 2; hf++) {
                    int rl = (wm * 2 + mf) * 16 + hf * 8 + gid;
                    int row = rowBase + rl;
                    if (row < M) {
                        als[row * H + hd] = ps[mf][hf][0] + sred[rl * 2 + 0];
                        ald[row * H + hd] = ps[mf][hf][1] + sred[rl * 2 + 1];
                    }
                }
        }
    }
}

// ---------------------------------------------------------------------------
// Single-block exclusive scan, 4 elements/thread (4096/iter). Pad of g_deg
// beyond N is permanently zero (never written), so int4 reads are safe.
// ---------------------------------------------------------------------------
__global__ __launch_bounds__(1024) void csr_scan_kernel(int N)
{
    __shared__ int wsum[32];
    __shared__ int carry;
    int tid = threadIdx.x;
    int lane = tid & 31, w = tid >> 5;
    if (tid == 0) { carry = 0; g_rowptr[0] = 0; }
    __syncthreads();
    for (int base = 0; base < N; base += 4096) {
        int i4 = base / 4 + tid;
        int4 v = make_int4(0, 0, 0, 0);
        if (i4 < MAXN / 4) v = ((const int4*)g_deg)[i4];
        int s4 = v.x + v.y + v.z + v.w;
        int x = s4;
#pragma unroll
        for (int off = 1; off < 32; off <<= 1) {
            int t = __shfl_up_sync(0xFFFFFFFF, x, off);
            if (lane >= off) x += t;
        }
        if (lane == 31) wsum[w] = x;
        __syncthreads();
        if (w == 0) {
            int s = wsum[lane];
#pragma unroll
            for (int off = 1; off < 32; off <<= 1) {
                int t = __shfl_up_sync(0xFFFFFFFF, s, off);
                if (lane >= off) s += t;
            }
            wsum[lane] = s;
        }
        __syncthreads();
        int incl = x + (w > 0 ? wsum[w - 1] : 0);
        int c = carry;
        int e = c + incl - s4;
        int idx = i4 * 4;
        if (idx < N)     { g_cursor[idx]     = e; g_rowptr[idx + 1] = e + v.x; }
        e += v.x;
        if (idx + 1 < N) { g_cursor[idx + 1] = e; g_rowptr[idx + 2] = e + v.y; }
        e += v.y;
        if (idx + 2 < N) { g_cursor[idx + 2] = e; g_rowptr[idx + 3] = e + v.z; }
        e += v.z;
        if (idx + 3 < N) { g_cursor[idx + 3] = e; g_rowptr[idx + 4] = e + v.w; }
        __syncthreads();
        if (tid == 1023) carry = c + incl;
        __syncthreads();
    }
}

// csr_fill fused with layer-1 edge exp, 2 edges per thread (MLP=2 on the
// atomic + scattered-gather latency chains). als/ald from GEMM1 are ready.
__global__ void csr_fill_ex4_kernel(const int* __restrict__ ei, int E,
                                    const float* __restrict__ als,
                                    const float* __restrict__ ald)
{
    int e0 = (blockIdx.x * blockDim.x + threadIdx.x) * 2;
    if (e0 >= E) return;
    bool two = (e0 + 1 < E);
    int2 ss = *(const int2*)&ei[e0];
    int2 dd = *(const int2*)&ei[E + e0];
    int p0 = atomicAdd(&g_cursor[dd.x], 1);
    int p1 = two ? atomicAdd(&g_cursor[dd.y], 1) : 0;
    float4 a0 = *(const float4*)&als[ss.x * 4];
    float4 b0 = *(const float4*)&ald[dd.x * 4];
    float4 a1 = two ? *(const float4*)&als[ss.y * 4] : make_float4(0, 0, 0, 0);
    float4 b1 = two ? *(const float4*)&ald[dd.y * 4] : make_float4(0, 0, 0, 0);

    g_col[p0] = ss.x;
    g_dst[p0] = dd.x;
    float4 v;
    v.x = a0.x + b0.x; v.x = (v.x > 0.f) ? v.x : 0.2f * v.x; v.x = __expf(v.x);
    v.y = a0.y + b0.y; v.y = (v.y > 0.f) ? v.y : 0.2f * v.y; v.y = __expf(v.y);
    v.z = a0.z + b0.z; v.z = (v.z > 0.f) ? v.z : 0.2f * v.z; v.z = __expf(v.z);
    v.w = a0.w + b0.w; v.w = (v.w > 0.f) ? v.w : 0.2f * v.w; v.w = __expf(v.w);
    *(float4*)&g_ex[(size_t)p0 * 4] = v;

    if (two) {
        g_col[p1] = ss.y;
        g_dst[p1] = dd.y;
        v.x = a1.x + b1.x; v.x = (v.x > 0.f) ? v.x : 0.2f * v.x; v.x = __expf(v.x);
        v.y = a1.y + b1.y; v.y = (v.y > 0.f) ? v.y : 0.2f * v.y; v.y = __expf(v.y);
        v.z = a1.z + b1.z; v.z = (v.z > 0.f) ? v.z : 0.2f * v.z; v.z = __expf(v.z);
        v.w = a1.w + b1.w; v.w = (v.w > 0.f) ? v.w : 0.2f * v.w; v.w = __expf(v.w);
        *(float4*)&g_ex[(size_t)p1 * 4] = v;
    }
}

// ---------------------------------------------------------------------------
// Edge exp (layers 2/3): ex[p,h] = exp(leaky_relu(als[src]+ald[dst])).
// ---------------------------------------------------------------------------
__global__ void edge_ex4_kernel(int E, const float* __restrict__ als,
                                const float* __restrict__ ald)
{
    int p = blockIdx.x * blockDim.x + threadIdx.x;
    if (p >= E) return;
    int s = g_col[p], d = g_dst[p];
    float4 a = *(const float4*)&als[s * 4];
    float4 b = *(const float4*)&ald[d * 4];
    float4 v;
    v.x = a.x + b.x; v.x = (v.x > 0.f) ? v.x : 0.2f * v.x; v.x = __expf(v.x);
    v.y = a.y + b.y; v.y = (v.y > 0.f) ? v.y : 0.2f * v.y; v.y = __expf(v.y);
    v.z = a.z + b.z; v.z = (v.z > 0.f) ? v.z : 0.2f * v.z; v.z = __expf(v.z);
    v.w = a.w + b.w; v.w = (v.w > 0.f) ? v.w : 0.2f * v.w; v.w = __expf(v.w);
    *(float4*)&g_ex[(size_t)p * 4] = v;
}

__global__ void edge_ex1_kernel(int E, const float* __restrict__ als,
                                const float* __restrict__ ald)
{
    int p = blockIdx.x * blockDim.x + threadIdx.x;
    if (p >= E) return;
    float v = als[g_col[p]] + ald[g_dst[p]];
    v = (v > 0.f) ? v : 0.2f * v;
    g_ex[p] = __expf(v);
}

// ---------------------------------------------------------------------------
// Gather (fp16 messages) + softmax-normalize + bias + ELU. TPE = HC/8 threads
// per dst; one uint4 (8 halves) per edge per thread. Output fp16 (HALF_OUT,
// feeds next GEMM) or fp32 (final layer, feeds pooling).
// ---------------------------------------------------------------------------
__device__ __forceinline__ void unpack8(uint4 r, float* v)
{
    float2 p;
    p = __half22float2(*(__half2*)&r.x); v[0] = p.x; v[1] = p.y;
    p = __half22float2(*((__half2*)&r.x + 1)); v[2] = p.x; v[3] = p.y;
    p = __half22float2(*(__half2*)&r.z); v[4] = p.x; v[5] = p.y;
    p = __half22float2(*((__half2*)&r.z + 1)); v[6] = p.x; v[7] = p.y;
}

template <int H, int C, bool HALF_OUT>
__global__ __launch_bounds__(256) void gather_kernel(
    int N, const __half* __restrict__ h,
    const float* __restrict__ als, const float* __restrict__ ald,
    const float* __restrict__ bias, void* __restrict__ outv)
{
    constexpr int HC = H * C;
    constexpr int TPE = HC / 8;
    constexpr int DPB = 256 / TPE;
    int d = blockIdx.x * DPB + threadIdx.x / TPE;
    if (d >= N) return;
    int t = threadIdx.x % TPE;
    int hd = t / (C / 8);

    // self-loop
    float l = als[d * H + hd] + ald[d * H + hd];
    l = (l > 0.f) ? l : 0.2f * l;
    float exs = __expf(l);
    float den = exs;
    float acc[8], v[8];
    uint4 raw = *(const uint4*)(h + (size_t)d * HC + t * 8);
    unpack8(raw, v);
#pragma unroll
    for (int i = 0; i < 8; i++) acc[i] = exs * v[i];

    int p = g_rowptr[d], pend = g_rowptr[d + 1];
    for (; p < pend; p++) {
        int s = g_col[p];
        float ex = g_ex[(size_t)p * H + hd];
        raw = *(const uint4*)(h + (size_t)s * HC + t * 8);
        unpack8(raw, v);
#pragma unroll
        for (int i = 0; i < 8; i++) acc[i] += ex * v[i];
        den += ex;
    }
    float inv = 1.f / (den + 1e-16f);
    float4 bv0 = *(const float4*)(bias + t * 8);
    float4 bv1 = *(const float4*)(bias + t * 8 + 4);
    float bb[8] = {bv0.x, bv0.y, bv0.z, bv0.w, bv1.x, bv1.y, bv1.z, bv1.w};
    float o[8];
#pragma unroll
    for (int i = 0; i < 8; i++) {
        float x = acc[i] * inv + bb[i];
        o[i] = (x > 0.f) ? x : expm1f(x);
    }
    if (HALF_OUT) {
        __half2 ho[4];
#pragma unroll
        for (int i = 0; i < 4; i++) ho[i] = __floats2half2_rn(o[2 * i], o[2 * i + 1]);
        *(uint4*)((__half*)outv + (size_t)d * HC + t * 8) = *(uint4*)ho;
    } else {
        float* op = (float*)outv + (size_t)d * HC + t * 8;
        *(float4*)op = make_float4(o[0], o[1], o[2], o[3]);
        *(float4*)(op + 4) = make_float4(o[4], o[5], o[6], o[7]);
    }
}

// ---------------------------------------------------------------------------
// Pooling (batch is sorted): run-length local accumulate, rare atomic flush.
// Also re-zeroes g_deg (dead by now) for the NEXT graph replay.
// ---------------------------------------------------------------------------
__global__ __launch_bounds__(256) void pool_acc_kernel(
    const float* __restrict__ h, const int* __restrict__ batch, int N)
{
    int gidx = blockIdx.x * 256 + threadIdx.x;
    if (gidx < N) g_deg[gidx] = 0;     // cleanup for next replay

    int c = threadIdx.x & 63;
    int lane = threadIdx.x >> 6;
    int n0 = blockIdx.x * 64 + lane * 16;
    float acc = 0.f;
    int curg = -1, cnt = 0;
    for (int k = 0; k < 16; k++) {
        int n = n0 + k;
        if (n >= N) break;
        int g = batch[n];
        if (g != curg) {
            if (curg >= 0) {
                atomicAdd(&g_pool[curg * 64 + c], acc);
                if (c == 0) atomicAdd(&g_cnt[curg], (float)cnt);
            }
            curg = g; acc = 0.f; cnt = 0;
        }
        acc += h[(size_t)n * 64 + c];
        cnt++;
    }
    if (curg >= 0) {
        atomicAdd(&g_pool[curg * 64 + c], acc);
        if (c == 0) atomicAdd(&g_cnt[curg], (float)cnt);
    }
}

// Single block (640 threads): compute output, then re-zero g_pool/g_cnt for
// the next replay (block-wide sync makes the read-then-zero race-free).
__global__ __launch_bounds__(640) void final_linear_kernel(
    const float* __restrict__ linW, const float* __restrict__ linb,
    float* __restrict__ out)
{
    int idx = threadIdx.x;
    if (idx < 640) {
        int g = idx / 10, o = idx % 10;
        float inv = 1.f / fmaxf(g_cnt[g], 1.f);
        float s = 0.f;
#pragma unroll 8
        for (int k = 0; k < 64; k++)
            s += g_pool[g * 64 + k] * inv * linW[k * 10 + o];
        out[idx] = s + linb[o];
    }
    __syncthreads();
    for (int i = threadIdx.x; i < 64 * 64; i += 640) g_pool[i] = 0.f;
    if (threadIdx.x < 64) g_cnt[threadIdx.x] = 0.f;
}

// ---------------------------------------------------------------------------
// Host orchestration (single stream; fill_ex is user launch #4 — profiled).
// ---------------------------------------------------------------------------
extern "C" void kernel_launch(void* const* d_in, const int* in_sizes, int n_in,
                              void* d_out, int out_size)
{
    const float* x     = (const float*)d_in[0];
    const int*   ei    = (const int*)d_in[1];
    const int*   batch = (const int*)d_in[2];
    const float* W1 = (const float*)d_in[3];   const float* b1 = (const float*)d_in[4];
    const float* as1 = (const float*)d_in[5];  const float* ad1 = (const float*)d_in[6];
    const float* W2 = (const float*)d_in[7];   const float* b2 = (const float*)d_in[8];
    const float* as2 = (const float*)d_in[9];  const float* ad2 = (const float*)d_in[10];
    const float* W3 = (const float*)d_in[11];  const float* b3 = (const float*)d_in[12];
    const float* as3 = (const float*)d_in[13]; const float* ad3 = (const float*)d_in[14];
    const float* linW = (const float*)d_in[15]; const float* linb = (const float*)d_in[16];
    float* out = (float*)d_out;

    int N = in_sizes[0] / 128;
    int E = in_sizes[1] / 2;

    float *als, *ald, *hB3;
    __half *hH, *hG, *xh, *Wh;
    cudaGetSymbolAddress((void**)&hH,  g_hH);
    cudaGetSymbolAddress((void**)&hG,  g_hG);
    cudaGetSymbolAddress((void**)&hB3, g_hB3);
    cudaGetSymbolAddress((void**)&als, g_als);
    cudaGetSymbolAddress((void**)&ald, g_ald);
    cudaGetSymbolAddress((void**)&xh,  g_xh);
    cudaGetSymbolAddress((void**)&Wh,  g_Wh);

    int gemmRows = (N + 127) / 128;

    // 1: prep (converts + degree histogram; g_deg pre-zeroed by prior replay)
    prep_kernel<<<(N * 32 + 255) / 256, 256>>>(x, W1, W2, W3, ei, N, E);

    // 2: layer-1 GEMM (+ fused attn coefs)
    h16_gemm_kernel<<<dim3(4, gemmRows), 256>>>(xh, Wh, hH, N, 256, 128,
                                                as1, ad1, als, ald, 4);
    // 3: CSR scan   4: fill + layer-1 edge exp (2 edges/thread)  <-- profiled
    csr_scan_kernel<<<1, 1024>>>(N);
    csr_fill_ex4_kernel<<<(E / 2 + 255) / 256, 256>>>(ei, E, als, ald);

    // Layer 1 gather (fp16 out: feeds GEMM2)
    gather_kernel<4, 64, true><<<(N + 7) / 8, 256>>>(N, hH, als, ald, b1, hG);

    // Layer 2
    h16_gemm_kernel<<<dim3(4, gemmRows), 256>>>(hG, Wh + 32768, hH, N, 256, 256,
                                                as2, ad2, als, ald, 4);
    edge_ex4_kernel<<<(E + 255) / 256, 256>>>(E, als, ald);
    gather_kernel<4, 64, true><<<(N + 7) / 8, 256>>>(N, hH, als, ald, b2, hG);

    // Layer 3 (fp32 out: feeds pooling)
    h16_gemm_kernel<<<dim3(1, gemmRows), 256>>>(hG, Wh + 98304, hH, N, 64, 256,
                                                as3, ad3, als, ald, 1);
    edge_ex1_kernel<<<(E + 255) / 256, 256>>>(E, als, ald);
    gather_kernel<1, 64, false><<<(N + 31) / 32, 256>>>(N, hH, als, ald, b3, hB3);

    // Pool (+ g_deg cleanup) + final linear (+ g_pool/g_cnt cleanup)
    pool_acc_kernel<<<(N + 63) / 64, 256>>>(hB3, batch, N);
    final_linear_kernel<<<1, 640>>>(linW, linb, out);
}